// round 14
// baseline (speedup 1.0000x reference)
#include <cuda_runtime.h>
#include <cuda_fp16.h>
#include <math.h>

#define NN 100000
#define NPAD 100096            // 782 * 128
#define EE 1600000
#define HH 128
#define GG 1000
#define CC 10
#define NB_SCAN ((NN + 255) / 256)   // 391
#define KSTR 136               // smem row stride in fp16 (272B; ldsm conflict-free)
#define ASTR 24                // smem A slab stride for layer-0 pipeline

// ---------------- scratch ----------------
__device__ __align__(16) __half g_hha[NN * HH];      // h ping
__device__ __align__(16) __half g_hhb[NN * HH];      // h pong
__device__ __align__(16) __half g_a16[NPAD * HH];    // converted x (fp16)
__device__ __align__(16) float g_dinv[NN];
__device__ __align__(16) int g_cnt[NN];
__device__ __align__(16) int g_rowptr[NN];
__device__ __align__(16) int g_fill[NN];
__device__ __align__(16) int g_bsum[NB_SCAN];
__device__ __align__(16) int g_boff[NB_SCAN];
__device__ __align__(16) int g_col[EE];
__device__ __align__(16) unsigned g_pool[GG * HH];

// ---------------- one-time stream/event infra (no device memory) ----------------
static cudaStream_t s_side = nullptr;
static cudaEvent_t s_e0 = nullptr, s_edinv = nullptr, s_ecsr = nullptr;
static bool s_ok = false;
struct _InitStreams {
    _InitStreams() {
        bool ok = cudaStreamCreateWithFlags(&s_side, cudaStreamNonBlocking) == cudaSuccess;
        ok = ok && cudaEventCreateWithFlags(&s_e0, cudaEventDisableTiming) == cudaSuccess;
        ok = ok && cudaEventCreateWithFlags(&s_edinv, cudaEventDisableTiming) == cudaSuccess;
        ok = ok && cudaEventCreateWithFlags(&s_ecsr, cudaEventDisableTiming) == cudaSuccess;
        s_ok = ok;
    }
};
static _InitStreams _init_streams;

// ---------------- init (fused: pool + deg counters) ----------------
__global__ void init_all() {
    int j = blockIdx.x * blockDim.x + threadIdx.x;
    if (j < GG * HH) g_pool[j] = 0x007FFFFFu;  // enc(-inf)
    if (j < NN) g_cnt[j] = 0;
}
__global__ void deg_count(const int* __restrict__ ei) {
    int e = blockIdx.x * blockDim.x + threadIdx.x;
    if (e < EE) atomicAdd(&g_cnt[ei[EE + e]], 1);
}

// ---------------- exclusive scan (scan1 also emits dinv) ----------------
__global__ void scan1() {
    __shared__ int s[256];
    int tid = threadIdx.x;
    int i = blockIdx.x * 256 + tid;
    int v = (i < NN) ? g_cnt[i] : 0;
    if (i < NN) g_dinv[i] = rsqrtf(1.0f + (float)v);
    s[tid] = v;
    __syncthreads();
#pragma unroll
    for (int off = 1; off < 256; off <<= 1) {
        int t = (tid >= off) ? s[tid - off] : 0;
        __syncthreads();
        s[tid] += t;
        __syncthreads();
    }
    if (i < NN) g_rowptr[i] = s[tid] - v;
    if (tid == 255) g_bsum[blockIdx.x] = s[255];
}
__global__ void scan2() {
    __shared__ int s[512];
    int tid = threadIdx.x;
    int v = (tid < NB_SCAN) ? g_bsum[tid] : 0;
    s[tid] = v;
    __syncthreads();
#pragma unroll
    for (int off = 1; off < 512; off <<= 1) {
        int t = (tid >= off) ? s[tid - off] : 0;
        __syncthreads();
        s[tid] += t;
        __syncthreads();
    }
    if (tid < NB_SCAN) g_boff[tid] = s[tid] - v;
}
__global__ void scan3() {
    int i = blockIdx.x * blockDim.x + threadIdx.x;
    if (i < NN) {
        g_rowptr[i] += g_boff[i >> 8];
        g_fill[i] = 0;
    }
}
__global__ void csr_fill(const int* __restrict__ ei) {
    int e = blockIdx.x * blockDim.x + threadIdx.x;
    if (e < EE) {
        int s = ei[e];
        int d = ei[EE + e];
        int pos = g_rowptr[d] + atomicAdd(&g_fill[d], 1);
        g_col[pos] = s;
    }
}

// ---------------- x -> fp16 (covers padding) ----------------
__global__ void convert_x(const float* __restrict__ X) {
    int i = blockIdx.x * blockDim.x + threadIdx.x;  // over NPAD*64 float2
    if (i < NPAD * 64) {
        float2 v = (i < NN * 64) ? ((const float2*)X)[i] : make_float2(0.f, 0.f);
        ((__half2*)g_a16)[i] = __floats2half2_rn(v.x, v.y);
    }
}

// ---------------- mma helpers ----------------
__device__ __forceinline__ void mma_f16(float c[4], unsigned a0, unsigned a1,
                                        unsigned a2, unsigned a3, unsigned b0,
                                        unsigned b1) {
    asm volatile(
        "mma.sync.aligned.m16n8k16.row.col.f32.f16.f16.f32 "
        "{%0,%1,%2,%3}, {%4,%5,%6,%7}, {%8,%9}, {%0,%1,%2,%3};"
        : "+f"(c[0]), "+f"(c[1]), "+f"(c[2]), "+f"(c[3])
        : "r"(a0), "r"(a1), "r"(a2), "r"(a3), "r"(b0), "r"(b1));
}
__device__ __forceinline__ void ldsm4t(unsigned& r0, unsigned& r1, unsigned& r2,
                                       unsigned& r3, unsigned saddr) {
    asm volatile(
        "ldmatrix.sync.aligned.m8n8.x4.trans.shared.b16 {%0,%1,%2,%3}, [%4];"
        : "=r"(r0), "=r"(r1), "=r"(r2), "=r"(r3)
        : "r"(saddr));
}
__device__ __forceinline__ void ldsm4(unsigned& r0, unsigned& r1, unsigned& r2,
                                      unsigned& r3, unsigned saddr) {
    asm volatile(
        "ldmatrix.sync.aligned.m8n8.x4.shared.b16 {%0,%1,%2,%3}, [%4];"
        : "=r"(r0), "=r"(r1), "=r"(r2), "=r"(r3)
        : "r"(saddr));
}

// ---------------- layer-0 GEMM (x fp16 in g_a16, cp.async A pipeline) ----------
__device__ __forceinline__ void stageA(unsigned sa0, int buf, const __half* aP,
                                       int k0, int tid) {
    int row = tid >> 1;
    int half = tid & 1;
    const __half* src = aP + row * 128 + k0 + half * 8;
    unsigned dst = sa0 + ((unsigned)((buf * 128 + row) * ASTR + half * 8)) * 2;
    asm volatile("cp.async.cg.shared.global [%0], [%1], 16;\n" ::"r"(dst),
                 "l"(src));
}

__global__ __launch_bounds__(256, 2) void gemm_mma(const float* __restrict__ W,
                                                   __half* __restrict__ hout) {
    extern __shared__ __half sw[];
    __half* Wh = sw;  // [128][KSTR]
    int tid = threadIdx.x;

    unsigned sbase = (unsigned)__cvta_generic_to_shared(sw);
    unsigned swh = sbase;
    unsigned sa0 = sbase + 128 * KSTR * 2;

    int row0 = blockIdx.x * 128;
    const __half* aP = g_a16 + (size_t)row0 * 128;

    stageA(sa0, 0, aP, 0, tid);
    asm volatile("cp.async.commit_group;\n");
    stageA(sa0, 1, aP, 16, tid);
    asm volatile("cp.async.commit_group;\n");

    for (int i = tid; i < 128 * 128; i += 256) {
        int k = i >> 7, n = i & 127;
        Wh[k * KSTR + n] = __float2half(W[i]);
    }
    __syncthreads();

    int warp = tid >> 5, lane = tid & 31;
    int g = lane >> 2, t = lane & 3;
    int q = lane >> 3, r = lane & 7;
    int kk_off = (r + ((q & 1) << 3)) * (KSTR * 2);
    int nn_off = ((q >> 1) << 3) * 2;
    unsigned aoff = ((unsigned)((warp * 16 + (lane & 15)) * ASTR + ((lane & 16) >> 1))) * 2;

    float c[16][4];
#pragma unroll
    for (int i = 0; i < 16; i++)
#pragma unroll
        for (int j = 0; j < 4; j++) c[i][j] = 0.f;

    for (int kb = 0; kb < 8; kb++) {
        if (kb < 7)
            asm volatile("cp.async.wait_group 1;\n");
        else
            asm volatile("cp.async.wait_group 0;\n");
        __syncthreads();

        int buf = kb & 1;
        unsigned ah0, ah1, ah2, ah3;
        ldsm4(ah0, ah1, ah2, ah3, sa0 + (unsigned)(buf * 128 * ASTR) * 2 + aoff);

        unsigned kbase = (unsigned)(kb * 16 * (KSTR * 2)) + kk_off + nn_off;
#pragma unroll
        for (int p = 0; p < 8; p++) {
            unsigned noff = kbase + p * 32;
            unsigned bh0, bh1, bh2, bh3;
            ldsm4t(bh0, bh1, bh2, bh3, swh + noff);
            mma_f16(c[2 * p],     ah0, ah1, ah2, ah3, bh0, bh1);
            mma_f16(c[2 * p + 1], ah0, ah1, ah2, ah3, bh2, bh3);
        }
        __syncthreads();
        if (kb < 6) {
            stageA(sa0, buf, aP, (kb + 2) * 16, tid);
            asm volatile("cp.async.commit_group;\n");
        }
    }

    int ra = row0 + warp * 16 + g, rb = ra + 8;
    float da = (ra < NN) ? g_dinv[ra] : 0.f;
    float db = (rb < NN) ? g_dinv[rb] : 0.f;
#pragma unroll
    for (int nt = 0; nt < 16; nt++) {
        int col = nt * 8 + t * 2;
        if (ra < NN)
            *(__half2*)&hout[(size_t)ra * 128 + col] =
                __floats2half2_rn(da * c[nt][0], da * c[nt][1]);
        if (rb < NN)
            *(__half2*)&hout[(size_t)rb * 128 + col] =
                __floats2half2_rn(db * c[nt][2], db * c[nt][3]);
    }
}

// ---------------- fused gather + GEMM (layers 1,2) ------------------------------
// Each block: gather its 128 rows (agg + self + bias + ELU) into smem A (fp16),
// then GEMM A @ W -> hout (dinv-prescaled fp16).
__global__ __launch_bounds__(256, 2) void fused_gg(const __half* __restrict__ hin,
                                                   __half* __restrict__ hout,
                                                   const float* __restrict__ bias,
                                                   const float* __restrict__ W) {
    extern __shared__ __half sw[];
    __half* Wh = sw;               // [128][KSTR]
    __half* Ah = sw + 128 * KSTR;  // [128][KSTR]
    int tid = threadIdx.x, warp = tid >> 5, lane = tid & 31;
    int row0 = blockIdx.x * 128;

    // stage W (fp32 -> fp16)
    for (int i = tid; i < 128 * 128; i += 256) {
        int k = i >> 7, n = i & 127;
        Wh[k * KSTR + n] = __float2half(W[i]);
    }

    // ---- gather phase: warp handles rows warp*16 .. warp*16+15 ----
    const uint2* h2 = (const uint2*)hin;  // 8B per lane = 4 features
    float4 bb = *(const float4*)&bias[lane * 4];
    for (int rr = 0; rr < 16; rr++) {
        int rl = warp * 16 + rr;
        int d = row0 + rl;
        float vx = 0.f, vy = 0.f, vz = 0.f, vw = 0.f;
        if (d < NN) {
            int beg = g_rowptr[d];
            int n_all = g_cnt[d];
            float4 acc = make_float4(0.f, 0.f, 0.f, 0.f);
            for (int b0 = 0; b0 < n_all; b0 += 32) {
                int n = min(32, n_all - b0);
                int c = (lane < n) ? g_col[beg + b0 + lane] : 0;
                int j = 0;
                for (; j + 4 <= n; j += 4) {
                    int s0 = __shfl_sync(0xffffffffu, c, j);
                    int s1 = __shfl_sync(0xffffffffu, c, j + 1);
                    int s2 = __shfl_sync(0xffffffffu, c, j + 2);
                    int s3 = __shfl_sync(0xffffffffu, c, j + 3);
                    uint2 v0 = h2[(size_t)s0 * 32 + lane];
                    uint2 v1 = h2[(size_t)s1 * 32 + lane];
                    uint2 v2 = h2[(size_t)s2 * 32 + lane];
                    uint2 v3 = h2[(size_t)s3 * 32 + lane];
                    float2 a0 = __half22float2(*(__half2*)&v0.x);
                    float2 c0 = __half22float2(*(__half2*)&v0.y);
                    float2 a1 = __half22float2(*(__half2*)&v1.x);
                    float2 c1 = __half22float2(*(__half2*)&v1.y);
                    float2 a2 = __half22float2(*(__half2*)&v2.x);
                    float2 c2 = __half22float2(*(__half2*)&v2.y);
                    float2 a3 = __half22float2(*(__half2*)&v3.x);
                    float2 c3 = __half22float2(*(__half2*)&v3.y);
                    acc.x += (a0.x + a1.x) + (a2.x + a3.x);
                    acc.y += (a0.y + a1.y) + (a2.y + a3.y);
                    acc.z += (c0.x + c1.x) + (c2.x + c3.x);
                    acc.w += (c0.y + c1.y) + (c2.y + c3.y);
                }
                for (; j < n; j++) {
                    int s = __shfl_sync(0xffffffffu, c, j);
                    uint2 hv = h2[(size_t)s * 32 + lane];
                    float2 f0 = __half22float2(*(__half2*)&hv.x);
                    float2 f1 = __half22float2(*(__half2*)&hv.y);
                    acc.x += f0.x;
                    acc.y += f0.y;
                    acc.z += f1.x;
                    acc.w += f1.y;
                }
            }
            float dd = g_dinv[d];
            uint2 hsv = h2[(size_t)d * 32 + lane];
            float2 s0 = __half22float2(*(__half2*)&hsv.x);
            float2 s1 = __half22float2(*(__half2*)&hsv.y);
            vx = dd * (acc.x + s0.x) + bb.x;
            vy = dd * (acc.y + s0.y) + bb.y;
            vz = dd * (acc.z + s1.x) + bb.z;
            vw = dd * (acc.w + s1.y) + bb.w;
            vx = vx > 0.f ? vx : expm1f(vx);
            vy = vy > 0.f ? vy : expm1f(vy);
            vz = vz > 0.f ? vz : expm1f(vz);
            vw = vw > 0.f ? vw : expm1f(vw);
        }
        // write activation row to smem A (same fp16 rounding as before)
        *(__half2*)&Ah[rl * KSTR + lane * 4] = __floats2half2_rn(vx, vy);
        *(__half2*)&Ah[rl * KSTR + lane * 4 + 2] = __floats2half2_rn(vz, vw);
    }
    __syncthreads();

    // ---- mma phase ----
    unsigned sbase = (unsigned)__cvta_generic_to_shared(sw);
    unsigned swh = sbase;
    unsigned sah = sbase + (unsigned)(128 * KSTR) * 2;
    int g = lane >> 2, t = lane & 3;
    int q = lane >> 3, r = lane & 7;
    int kk_off = (r + ((q & 1) << 3)) * (KSTR * 2);
    int nn_off = ((q >> 1) << 3) * 2;
    unsigned aoff = ((unsigned)((warp * 16 + (lane & 15)) * KSTR + ((lane & 16) >> 1))) * 2;

    float c[16][4];
#pragma unroll
    for (int i = 0; i < 16; i++)
#pragma unroll
        for (int j = 0; j < 4; j++) c[i][j] = 0.f;

#pragma unroll
    for (int kb = 0; kb < 8; kb++) {
        unsigned ah0, ah1, ah2, ah3;
        ldsm4(ah0, ah1, ah2, ah3, sah + aoff + (unsigned)(kb * 32));
        unsigned kbase = (unsigned)(kb * 16 * (KSTR * 2)) + kk_off + nn_off;
#pragma unroll
        for (int p = 0; p < 8; p++) {
            unsigned noff = kbase + p * 32;
            unsigned bh0, bh1, bh2, bh3;
            ldsm4t(bh0, bh1, bh2, bh3, swh + noff);
            mma_f16(c[2 * p],     ah0, ah1, ah2, ah3, bh0, bh1);
            mma_f16(c[2 * p + 1], ah0, ah1, ah2, ah3, bh2, bh3);
        }
    }

    int ra = row0 + warp * 16 + g, rb = ra + 8;
    float da = (ra < NN) ? g_dinv[ra] : 0.f;
    float db = (rb < NN) ? g_dinv[rb] : 0.f;
#pragma unroll
    for (int nt = 0; nt < 16; nt++) {
        int col = nt * 8 + t * 2;
        if (ra < NN)
            *(__half2*)&hout[(size_t)ra * 128 + col] =
                __floats2half2_rn(da * c[nt][0], da * c[nt][1]);
        if (rb < NN)
            *(__half2*)&hout[(size_t)rb * 128 + col] =
                __floats2half2_rn(db * c[nt][2], db * c[nt][3]);
    }
}

// ---------------- pool encode ----------------
__device__ __forceinline__ unsigned enc_f(float x) {
    unsigned u = __float_as_uint(x);
    return (u & 0x80000000u) ? ~u : (u | 0x80000000u);
}
__device__ __forceinline__ float dec_f(unsigned e) {
    return (e & 0x80000000u) ? __uint_as_float(e ^ 0x80000000u)
                             : __uint_as_float(~e);
}

// ---------------- final gather (layer 3): aggregate + pool ----------------
__global__ void gather_pool(const __half* __restrict__ hin,
                            const float* __restrict__ bias,
                            const int* __restrict__ batch) {
    int warp = (blockIdx.x * blockDim.x + threadIdx.x) >> 5;
    int lane = threadIdx.x & 31;
    if (warp >= NN) return;
    int d = warp;
    int beg = g_rowptr[d];
    int end = beg + g_cnt[d];
    const uint2* h2 = (const uint2*)hin;

    float4 acc = make_float4(0.f, 0.f, 0.f, 0.f);
    for (int base = beg; base < end; base += 32) {
        int n = min(32, end - base);
        int c = (lane < n) ? g_col[base + lane] : 0;
        int j = 0;
        for (; j + 4 <= n; j += 4) {
            int s0 = __shfl_sync(0xffffffffu, c, j);
            int s1 = __shfl_sync(0xffffffffu, c, j + 1);
            int s2 = __shfl_sync(0xffffffffu, c, j + 2);
            int s3 = __shfl_sync(0xffffffffu, c, j + 3);
            uint2 v0 = h2[(size_t)s0 * 32 + lane];
            uint2 v1 = h2[(size_t)s1 * 32 + lane];
            uint2 v2 = h2[(size_t)s2 * 32 + lane];
            uint2 v3 = h2[(size_t)s3 * 32 + lane];
            float2 a0 = __half22float2(*(__half2*)&v0.x);
            float2 b0 = __half22float2(*(__half2*)&v0.y);
            float2 a1 = __half22float2(*(__half2*)&v1.x);
            float2 b1 = __half22float2(*(__half2*)&v1.y);
            float2 a2 = __half22float2(*(__half2*)&v2.x);
            float2 b2 = __half22float2(*(__half2*)&v2.y);
            float2 a3 = __half22float2(*(__half2*)&v3.x);
            float2 b3 = __half22float2(*(__half2*)&v3.y);
            acc.x += (a0.x + a1.x) + (a2.x + a3.x);
            acc.y += (a0.y + a1.y) + (a2.y + a3.y);
            acc.z += (b0.x + b1.x) + (b2.x + b3.x);
            acc.w += (b0.y + b1.y) + (b2.y + b3.y);
        }
        for (; j < n; j++) {
            int s = __shfl_sync(0xffffffffu, c, j);
            uint2 hv = h2[(size_t)s * 32 + lane];
            float2 f0 = __half22float2(*(__half2*)&hv.x);
            float2 f1 = __half22float2(*(__half2*)&hv.y);
            acc.x += f0.x;
            acc.y += f0.y;
            acc.z += f1.x;
            acc.w += f1.y;
        }
    }
    float dd = g_dinv[d];
    uint2 hsv = h2[(size_t)d * 32 + lane];
    float2 s0 = __half22float2(*(__half2*)&hsv.x);
    float2 s1 = __half22float2(*(__half2*)&hsv.y);
    float4 bb = *(const float4*)&bias[lane * 4];
    float vx = dd * (acc.x + s0.x) + bb.x;
    float vy = dd * (acc.y + s0.y) + bb.y;
    float vz = dd * (acc.z + s1.x) + bb.z;
    float vw = dd * (acc.w + s1.y) + bb.w;
    vx = vx > 0.f ? vx : expm1f(vx);
    vy = vy > 0.f ? vy : expm1f(vy);
    vz = vz > 0.f ? vz : expm1f(vz);
    vw = vw > 0.f ? vw : expm1f(vw);

    int g = batch[d];
    unsigned* p = &g_pool[g * 128 + lane * 4];
    atomicMax(&p[0], enc_f(vx));
    atomicMax(&p[1], enc_f(vy));
    atomicMax(&p[2], enc_f(vz));
    atomicMax(&p[3], enc_f(vw));
}

// ---------------- head ----------------
__global__ void head(const float* __restrict__ Wl, const float* __restrict__ bl,
                     float* __restrict__ out) {
    int warp = (blockIdx.x * blockDim.x + threadIdx.x) >> 5;
    int lane = threadIdx.x & 31;
    if (warp >= GG) return;
    float part[CC];
#pragma unroll
    for (int c = 0; c < CC; c++) part[c] = 0.f;
    for (int f = lane; f < HH; f += 32) {
        float p = dec_f(g_pool[warp * HH + f]);
        if (p < -3.0e38f) p = 0.0f;
#pragma unroll
        for (int c = 0; c < CC; c++) part[c] += p * Wl[f * CC + c];
    }
#pragma unroll
    for (int c = 0; c < CC; c++)
        for (int off = 16; off; off >>= 1)
            part[c] += __shfl_xor_sync(0xffffffffu, part[c], off);
    if (lane == 0) {
        float lg[CC];
        float m = -3.4e38f;
#pragma unroll
        for (int c = 0; c < CC; c++) {
            lg[c] = part[c] + bl[c];
            m = fmaxf(m, lg[c]);
        }
        float sum = 0.f;
#pragma unroll
        for (int c = 0; c < CC; c++) {
            lg[c] = expf(lg[c] - m);
            sum += lg[c];
        }
        float inv = 1.0f / sum;
#pragma unroll
        for (int c = 0; c < CC; c++) out[warp * CC + c] = lg[c] * inv;
    }
}

// ---------------- launcher ----------------
extern "C" void kernel_launch(void* const* d_in, const int* in_sizes, int n_in,
                              void* d_out, int out_size) {
    const float* x = (const float*)d_in[0];
    const int* ei = (const int*)d_in[1];
    const int* batch = (const int*)d_in[2];
    const float* W0 = (const float*)d_in[3];
    const float* b0 = (const float*)d_in[4];
    const float* W1 = (const float*)d_in[5];
    const float* b1 = (const float*)d_in[6];
    const float* W2 = (const float*)d_in[7];
    const float* b2 = (const float*)d_in[8];
    const float* Wl = (const float*)d_in[9];
    const float* bl = (const float*)d_in[10];
    float* out = (float*)d_out;

    const int T = 256;
    const int gemm_smem = 128 * KSTR * 2 + 2 * 128 * ASTR * 2;   // 47104 B
    const int fused_smem = 2 * 128 * KSTR * 2;                   // 69632 B
    cudaFuncSetAttribute(gemm_mma, cudaFuncAttributeMaxDynamicSharedMemorySize,
                         gemm_smem);
    cudaFuncSetAttribute(fused_gg, cudaFuncAttributeMaxDynamicSharedMemorySize,
                         fused_smem);

    const int gemm_blocks = NPAD / 128;  // 782
    const int gather_blocks = (NN * 32 + T - 1) / T;

    init_all<<<(GG * HH + T - 1) / T, T>>>();

    if (s_ok) {
        cudaEventRecord(s_e0, 0);
        cudaStreamWaitEvent(s_side, s_e0, 0);
        deg_count<<<(EE + T - 1) / T, T, 0, s_side>>>(ei);
        scan1<<<NB_SCAN, 256, 0, s_side>>>();
        cudaEventRecord(s_edinv, s_side);          // g_dinv ready
        scan2<<<1, 512, 0, s_side>>>();
        scan3<<<(NN + T - 1) / T, T, 0, s_side>>>();
        csr_fill<<<(EE + T - 1) / T, T, 0, s_side>>>(ei);
        cudaEventRecord(s_ecsr, s_side);           // CSR ready

        convert_x<<<(NPAD * 64 + T - 1) / T, T>>>(x);
        cudaStreamWaitEvent(0, s_edinv, 0);        // RACE FIX: gemm0 reads g_dinv
        gemm_mma<<<gemm_blocks, T, gemm_smem>>>(W0, g_hha);
        cudaStreamWaitEvent(0, s_ecsr, 0);         // join before first gather
    } else {
        deg_count<<<(EE + T - 1) / T, T>>>(ei);
        scan1<<<NB_SCAN, 256>>>();
        scan2<<<1, 512>>>();
        scan3<<<(NN + T - 1) / T, T>>>();
        csr_fill<<<(EE + T - 1) / T, T>>>(ei);
        convert_x<<<(NPAD * 64 + T - 1) / T, T>>>(x);
        gemm_mma<<<gemm_blocks, T, gemm_smem>>>(W0, g_hha);
    }

    fused_gg<<<gemm_blocks, T, fused_smem>>>(g_hha, g_hhb, b0, W1);
    fused_gg<<<gemm_blocks, T, fused_smem>>>(g_hhb, g_hha, b1, W2);
    gather_pool<<<gather_blocks, T>>>(g_hha, b2, batch);
    head<<<(GG + 7) / 8, T>>>(Wl, bl, out);
}

// round 16
// speedup vs baseline: 20.7206x; 20.7206x over previous
#include <cuda_runtime.h>
#include <cuda_fp16.h>
#include <math.h>

#define NN 100000
#define NPAD 100096            // 782 * 128
#define EE 1600000
#define HH 128
#define GG 1000
#define CC 10
#define NB_SCAN ((NN + 255) / 256)   // 391
#define KSTR 136               // smem W row stride in fp16 (272B, 16B-aligned)
#define ASTR 24                // smem A row stride in fp16 (48B: conflict-free ldsm)

// ---------------- scratch ----------------
__device__ __align__(16) __half g_hh[NN * HH];       // dinv-prescaled GEMM out (fp16)
__device__ __align__(16) __half g_a16[NPAD * HH];    // activations (fp16)
__device__ __align__(16) float g_dinv[NN];
__device__ __align__(16) int g_cnt[NN];
__device__ __align__(16) int g_rowptr[NN];
__device__ __align__(16) int g_fill[NN];
__device__ __align__(16) int g_bsum[NB_SCAN];
__device__ __align__(16) int g_boff[NB_SCAN];
__device__ __align__(16) int g_col[EE];
__device__ __align__(16) unsigned g_pool[GG * HH];

// ---------------- one-time stream/event infra (no device memory) ----------------
static cudaStream_t s_side = nullptr;
static cudaEvent_t s_e0 = nullptr, s_edinv = nullptr, s_ecsr = nullptr;
static bool s_ok = false;
struct _InitStreams {
    _InitStreams() {
        bool ok = cudaStreamCreateWithFlags(&s_side, cudaStreamNonBlocking) == cudaSuccess;
        ok = ok && cudaEventCreateWithFlags(&s_e0, cudaEventDisableTiming) == cudaSuccess;
        ok = ok && cudaEventCreateWithFlags(&s_edinv, cudaEventDisableTiming) == cudaSuccess;
        ok = ok && cudaEventCreateWithFlags(&s_ecsr, cudaEventDisableTiming) == cudaSuccess;
        s_ok = ok;
    }
};
static _InitStreams _init_streams;

// ---------------- init (fused: pool + deg counters) ----------------
__global__ void init_all() {
    int j = blockIdx.x * blockDim.x + threadIdx.x;
    if (j < GG * HH) g_pool[j] = 0x007FFFFFu;  // enc(-inf)
    if (j < NN) g_cnt[j] = 0;
}
__global__ void deg_count(const int* __restrict__ ei) {
    int e = blockIdx.x * blockDim.x + threadIdx.x;
    if (e < EE) atomicAdd(&g_cnt[ei[EE + e]], 1);
}

// ---------------- exclusive scan (scan1 also emits dinv) ----------------
__global__ void scan1() {
    __shared__ int s[256];
    int tid = threadIdx.x;
    int i = blockIdx.x * 256 + tid;
    int v = (i < NN) ? g_cnt[i] : 0;
    if (i < NN) g_dinv[i] = rsqrtf(1.0f + (float)v);
    s[tid] = v;
    __syncthreads();
#pragma unroll
    for (int off = 1; off < 256; off <<= 1) {
        int t = (tid >= off) ? s[tid - off] : 0;
        __syncthreads();
        s[tid] += t;
        __syncthreads();
    }
    if (i < NN) g_rowptr[i] = s[tid] - v;
    if (tid == 255) g_bsum[blockIdx.x] = s[255];
}
__global__ void scan2() {
    __shared__ int s[512];
    int tid = threadIdx.x;
    int v = (tid < NB_SCAN) ? g_bsum[tid] : 0;
    s[tid] = v;
    __syncthreads();
#pragma unroll
    for (int off = 1; off < 512; off <<= 1) {
        int t = (tid >= off) ? s[tid - off] : 0;
        __syncthreads();
        s[tid] += t;
        __syncthreads();
    }
    if (tid < NB_SCAN) g_boff[tid] = s[tid] - v;
}
__global__ void scan3() {
    int i = blockIdx.x * blockDim.x + threadIdx.x;
    if (i < NN) {
        g_rowptr[i] += g_boff[i >> 8];
        g_fill[i] = 0;
    }
}
__global__ void csr_fill(const int* __restrict__ ei) {
    int e = blockIdx.x * blockDim.x + threadIdx.x;
    if (e < EE) {
        int s = ei[e];
        int d = ei[EE + e];
        int pos = g_rowptr[d] + atomicAdd(&g_fill[d], 1);
        g_col[pos] = s;
    }
}

// ---------------- x -> fp16 (covers padding) ----------------
__global__ void convert_x(const float* __restrict__ X) {
    int i = blockIdx.x * blockDim.x + threadIdx.x;  // over NPAD*64 float2
    if (i < NPAD * 64) {
        float2 v = (i < NN * 64) ? ((const float2*)X)[i] : make_float2(0.f, 0.f);
        ((__half2*)g_a16)[i] = __floats2half2_rn(v.x, v.y);
    }
}

// ---------------- tensor-core GEMM (fp16 single-term, cp.async A pipeline) -----
__device__ __forceinline__ void mma_f16(float c[4], unsigned a0, unsigned a1,
                                        unsigned a2, unsigned a3, unsigned b0,
                                        unsigned b1) {
    asm volatile(
        "mma.sync.aligned.m16n8k16.row.col.f32.f16.f16.f32 "
        "{%0,%1,%2,%3}, {%4,%5,%6,%7}, {%8,%9}, {%0,%1,%2,%3};"
        : "+f"(c[0]), "+f"(c[1]), "+f"(c[2]), "+f"(c[3])
        : "r"(a0), "r"(a1), "r"(a2), "r"(a3), "r"(b0), "r"(b1));
}
__device__ __forceinline__ void ldsm4t(unsigned& r0, unsigned& r1, unsigned& r2,
                                       unsigned& r3, unsigned saddr) {
    asm volatile(
        "ldmatrix.sync.aligned.m8n8.x4.trans.shared.b16 {%0,%1,%2,%3}, [%4];"
        : "=r"(r0), "=r"(r1), "=r"(r2), "=r"(r3)
        : "r"(saddr));
}
__device__ __forceinline__ void ldsm4(unsigned& r0, unsigned& r1, unsigned& r2,
                                      unsigned& r3, unsigned saddr) {
    asm volatile(
        "ldmatrix.sync.aligned.m8n8.x4.shared.b16 {%0,%1,%2,%3}, [%4];"
        : "=r"(r0), "=r"(r1), "=r"(r2), "=r"(r3)
        : "r"(saddr));
}

// stage one 128x16 fp16 A slab into smem buffer `buf` via cp.async (256 thr)
__device__ __forceinline__ void stageA(unsigned sa0, int buf, const __half* aP,
                                       int k0, int tid) {
    int row = tid >> 1;   // 0..127
    int half = tid & 1;   // k-halves 0-7 / 8-15
    const __half* src = aP + row * 128 + k0 + half * 8;
    unsigned dst = sa0 + ((unsigned)((buf * 128 + row) * ASTR + half * 8)) * 2;
    asm volatile("cp.async.cg.shared.global [%0], [%1], 16;\n" ::"r"(dst),
                 "l"(src));
}

__global__ __launch_bounds__(256, 2) void gemm_mma(const float* __restrict__ W) {
    extern __shared__ __half sw[];
    __half* Wh = sw;  // [128][KSTR]
    int tid = threadIdx.x;

    unsigned sbase = (unsigned)__cvta_generic_to_shared(sw);
    unsigned swh = sbase;
    unsigned sa0 = sbase + 128 * KSTR * 2;  // A region: [2 buf][128][ASTR]

    int row0 = blockIdx.x * 128;
    const __half* aP = g_a16 + (size_t)row0 * 128;

    stageA(sa0, 0, aP, 0, tid);
    asm volatile("cp.async.commit_group;\n");
    stageA(sa0, 1, aP, 16, tid);
    asm volatile("cp.async.commit_group;\n");

    for (int i = tid; i < 128 * 128; i += 256) {
        int k = i >> 7, n = i & 127;
        Wh[k * KSTR + n] = __float2half(W[i]);
    }
    __syncthreads();

    int warp = tid >> 5, lane = tid & 31;
    int g = lane >> 2, t = lane & 3;

    int q = lane >> 3, r = lane & 7;
    int kk_off = (r + ((q & 1) << 3)) * (KSTR * 2);
    int nn_off = ((q >> 1) << 3) * 2;

    unsigned aoff = ((unsigned)((warp * 16 + (lane & 15)) * ASTR + ((lane & 16) >> 1))) * 2;

    float c[16][4];
#pragma unroll
    for (int i = 0; i < 16; i++)
#pragma unroll
        for (int j = 0; j < 4; j++) c[i][j] = 0.f;

    for (int kb = 0; kb < 8; kb++) {
        if (kb < 7)
            asm volatile("cp.async.wait_group 1;\n");
        else
            asm volatile("cp.async.wait_group 0;\n");
        __syncthreads();

        int buf = kb & 1;
        unsigned ah0, ah1, ah2, ah3;
        ldsm4(ah0, ah1, ah2, ah3, sa0 + (unsigned)(buf * 128 * ASTR) * 2 + aoff);

        unsigned kbase = (unsigned)(kb * 16 * (KSTR * 2)) + kk_off + nn_off;
#pragma unroll
        for (int p = 0; p < 8; p++) {
            unsigned noff = kbase + p * 32;
            unsigned bh0, bh1, bh2, bh3;
            ldsm4t(bh0, bh1, bh2, bh3, swh + noff);
            mma_f16(c[2 * p],     ah0, ah1, ah2, ah3, bh0, bh1);
            mma_f16(c[2 * p + 1], ah0, ah1, ah2, ah3, bh2, bh3);
        }
        __syncthreads();
        if (kb < 6) {
            stageA(sa0, buf, aP, (kb + 2) * 16, tid);
            asm volatile("cp.async.commit_group;\n");
        }
    }

    int ra = row0 + warp * 16 + g, rb = ra + 8;
    float da = (ra < NN) ? g_dinv[ra] : 0.f;
    float db = (rb < NN) ? g_dinv[rb] : 0.f;
#pragma unroll
    for (int nt = 0; nt < 16; nt++) {
        int col = nt * 8 + t * 2;
        if (ra < NN)
            *(__half2*)&g_hh[(size_t)ra * 128 + col] =
                __floats2half2_rn(da * c[nt][0], da * c[nt][1]);
        if (rb < NN)
            *(__half2*)&g_hh[(size_t)rb * 128 + col] =
                __floats2half2_rn(db * c[nt][2], db * c[nt][3]);
    }
}

// ---------------- pool encode ----------------
__device__ __forceinline__ unsigned enc_f(float x) {
    unsigned u = __float_as_uint(x);
    return (u & 0x80000000u) ? ~u : (u | 0x80000000u);
}
__device__ __forceinline__ float dec_f(unsigned e) {
    return (e & 0x80000000u) ? __uint_as_float(e ^ 0x80000000u)
                             : __uint_as_float(~e);
}

// ---------------- fused gather (fp16 h, prescaled; 8-deep load batch) ----------
__global__ void gather_fused(const float* __restrict__ bias,
                             const int* __restrict__ batch, int do_pool) {
    int warp = (blockIdx.x * blockDim.x + threadIdx.x) >> 5;
    int lane = threadIdx.x & 31;
    if (warp >= NN) return;
    int d = warp;
    int beg = g_rowptr[d];
    int end = beg + g_cnt[d];
    const uint2* h2 = (const uint2*)g_hh;  // 4 halves per uint2; 32 per row

    float4 acc = make_float4(0.f, 0.f, 0.f, 0.f);
    for (int base = beg; base < end; base += 32) {
        int n = min(32, end - base);
        int c = (lane < n) ? g_col[base + lane] : 0;
        int j = 0;
        for (; j + 8 <= n; j += 8) {
            uint2 v[8];
#pragma unroll
            for (int u = 0; u < 8; u++) {
                int s = __shfl_sync(0xffffffffu, c, j + u);
                v[u] = h2[(size_t)s * 32 + lane];
            }
#pragma unroll
            for (int u = 0; u < 8; u++) {
                float2 f0 = __half22float2(*(__half2*)&v[u].x);
                float2 f1 = __half22float2(*(__half2*)&v[u].y);
                acc.x += f0.x;
                acc.y += f0.y;
                acc.z += f1.x;
                acc.w += f1.y;
            }
        }
        for (; j < n; j++) {
            int s = __shfl_sync(0xffffffffu, c, j);
            uint2 hv = h2[(size_t)s * 32 + lane];
            float2 f0 = __half22float2(*(__half2*)&hv.x);
            float2 f1 = __half22float2(*(__half2*)&hv.y);
            acc.x += f0.x;
            acc.y += f0.y;
            acc.z += f1.x;
            acc.w += f1.y;
        }
    }
    float dd = g_dinv[d];
    uint2 hsv = h2[(size_t)d * 32 + lane];  // = dinv_d * h_d (fp16)
    float2 s0 = __half22float2(*(__half2*)&hsv.x);
    float2 s1 = __half22float2(*(__half2*)&hsv.y);
    float4 bb = *(const float4*)&bias[lane * 4];
    float vx = dd * (acc.x + s0.x) + bb.x;
    float vy = dd * (acc.y + s0.y) + bb.y;
    float vz = dd * (acc.z + s1.x) + bb.z;
    float vw = dd * (acc.w + s1.y) + bb.w;
    vx = vx > 0.f ? vx : expm1f(vx);
    vy = vy > 0.f ? vy : expm1f(vy);
    vz = vz > 0.f ? vz : expm1f(vz);
    vw = vw > 0.f ? vw : expm1f(vw);

    if (!do_pool) {
        __half2* pa = (__half2*)g_a16 + (size_t)d * 64 + lane * 2;
        pa[0] = __floats2half2_rn(vx, vy);
        pa[1] = __floats2half2_rn(vz, vw);
    } else {
        int g = batch[d];
        unsigned* p = &g_pool[g * 128 + lane * 4];
        atomicMax(&p[0], enc_f(vx));
        atomicMax(&p[1], enc_f(vy));
        atomicMax(&p[2], enc_f(vz));
        atomicMax(&p[3], enc_f(vw));
    }
}

// ---------------- head ----------------
__global__ void head(const float* __restrict__ Wl, const float* __restrict__ bl,
                     float* __restrict__ out) {
    int warp = (blockIdx.x * blockDim.x + threadIdx.x) >> 5;
    int lane = threadIdx.x & 31;
    if (warp >= GG) return;
    float part[CC];
#pragma unroll
    for (int c = 0; c < CC; c++) part[c] = 0.f;
    for (int f = lane; f < HH; f += 32) {
        float p = dec_f(g_pool[warp * HH + f]);
        if (p < -3.0e38f) p = 0.0f;
#pragma unroll
        for (int c = 0; c < CC; c++) part[c] += p * Wl[f * CC + c];
    }
#pragma unroll
    for (int c = 0; c < CC; c++)
        for (int off = 16; off; off >>= 1)
            part[c] += __shfl_xor_sync(0xffffffffu, part[c], off);
    if (lane == 0) {
        float lg[CC];
        float m = -3.4e38f;
#pragma unroll
        for (int c = 0; c < CC; c++) {
            lg[c] = part[c] + bl[c];
            m = fmaxf(m, lg[c]);
        }
        float sum = 0.f;
#pragma unroll
        for (int c = 0; c < CC; c++) {
            lg[c] = expf(lg[c] - m);
            sum += lg[c];
        }
        float inv = 1.0f / sum;
#pragma unroll
        for (int c = 0; c < CC; c++) out[warp * CC + c] = lg[c] * inv;
    }
}

// ---------------- launcher ----------------
extern "C" void kernel_launch(void* const* d_in, const int* in_sizes, int n_in,
                              void* d_out, int out_size) {
    const float* x = (const float*)d_in[0];
    const int* ei = (const int*)d_in[1];
    const int* batch = (const int*)d_in[2];
    const float* W0 = (const float*)d_in[3];
    const float* b0 = (const float*)d_in[4];
    const float* W1 = (const float*)d_in[5];
    const float* b1 = (const float*)d_in[6];
    const float* W2 = (const float*)d_in[7];
    const float* b2 = (const float*)d_in[8];
    const float* Wl = (const float*)d_in[9];
    const float* bl = (const float*)d_in[10];
    float* out = (float*)d_out;

    const int T = 256;
    const int gemm_smem = 128 * KSTR * 2 + 2 * 128 * ASTR * 2;  // 47104 B
    cudaFuncSetAttribute(gemm_mma, cudaFuncAttributeMaxDynamicSharedMemorySize,
                         gemm_smem);

    const int gemm_blocks = NPAD / 128;  // 782
    const int gather_blocks = (NN * 32 + T - 1) / T;

    init_all<<<(GG * HH + T - 1) / T, T>>>();

    if (s_ok) {
        // fork: CSR build on side stream, convert+gemm0 on main stream
        cudaEventRecord(s_e0, 0);
        cudaStreamWaitEvent(s_side, s_e0, 0);
        deg_count<<<(EE + T - 1) / T, T, 0, s_side>>>(ei);
        scan1<<<NB_SCAN, 256, 0, s_side>>>();
        cudaEventRecord(s_edinv, s_side);        // g_dinv ready
        scan2<<<1, 512, 0, s_side>>>();
        scan3<<<(NN + T - 1) / T, T, 0, s_side>>>();
        csr_fill<<<(EE + T - 1) / T, T, 0, s_side>>>(ei);
        cudaEventRecord(s_ecsr, s_side);         // CSR ready

        convert_x<<<(NPAD * 64 + T - 1) / T, T>>>(x);
        cudaStreamWaitEvent(0, s_edinv, 0);      // gemm0 epilogue reads g_dinv
        gemm_mma<<<gemm_blocks, T, gemm_smem>>>(W0);
        cudaStreamWaitEvent(0, s_ecsr, 0);       // join before first gather
    } else {
        deg_count<<<(EE + T - 1) / T, T>>>(ei);
        scan1<<<NB_SCAN, 256>>>();
        scan2<<<1, 512>>>();
        scan3<<<(NN + T - 1) / T, T>>>();
        csr_fill<<<(EE + T - 1) / T, T>>>(ei);
        convert_x<<<(NPAD * 64 + T - 1) / T, T>>>(x);
        gemm_mma<<<gemm_blocks, T, gemm_smem>>>(W0);
    }

    gather_fused<<<gather_blocks, T>>>(b0, batch, 0);
    gemm_mma<<<gemm_blocks, T, gemm_smem>>>(W1);
    gather_fused<<<gather_blocks, T>>>(b1, batch, 0);
    gemm_mma<<<gemm_blocks, T, gemm_smem>>>(W2);
    gather_fused<<<gather_blocks, T>>>(b2, batch, 1);

    head<<<(GG + 7) / 8, T>>>(Wl, bl, out);
}

// round 17
// speedup vs baseline: 21.4714x; 1.0362x over previous
#include <cuda_runtime.h>
#include <cuda_fp16.h>
#include <math.h>

#define NN 100000
#define NPAD 100096            // 782 * 128
#define EE 1600000
#define HH 128
#define GG 1000
#define CC 10
#define NB_SCAN ((NN + 255) / 256)   // 391
#define KSTR 136               // smem W row stride in fp16 (272B, 16B-aligned)
#define ASTR 24                // smem A row stride in fp16 (48B: conflict-free ldsm)

// ---------------- scratch ----------------
__device__ __align__(16) __half g_hh[NN * HH];       // dinv-prescaled GEMM out (fp16)
__device__ __align__(16) __half g_a16[NPAD * HH];    // activations (fp16)
__device__ __align__(16) float g_dinv[NN];
__device__ __align__(16) int g_cnt[NN];
__device__ __align__(16) int g_rowptr[NN];
__device__ __align__(16) int g_fill[NN];
__device__ __align__(16) int g_bsum[NB_SCAN];
__device__ __align__(16) int g_boff[NB_SCAN];
__device__ __align__(16) int g_col[EE];
__device__ __align__(16) unsigned g_pool[GG * HH];

// ---------------- one-time stream/event infra (no device memory) ----------------
static cudaStream_t s_side = nullptr;
static cudaEvent_t s_e0 = nullptr, s_edinv = nullptr, s_ecsr = nullptr;
static bool s_ok = false;
struct _InitStreams {
    _InitStreams() {
        bool ok = cudaStreamCreateWithFlags(&s_side, cudaStreamNonBlocking) == cudaSuccess;
        ok = ok && cudaEventCreateWithFlags(&s_e0, cudaEventDisableTiming) == cudaSuccess;
        ok = ok && cudaEventCreateWithFlags(&s_edinv, cudaEventDisableTiming) == cudaSuccess;
        ok = ok && cudaEventCreateWithFlags(&s_ecsr, cudaEventDisableTiming) == cudaSuccess;
        s_ok = ok;
    }
};
static _InitStreams _init_streams;

// ---------------- init (fused: pool + deg counters) ----------------
__global__ void init_all() {
    int j = blockIdx.x * blockDim.x + threadIdx.x;
    if (j < GG * HH) g_pool[j] = 0x007FFFFFu;  // enc(-inf)
    if (j < NN) g_cnt[j] = 0;
}
__global__ void deg_count(const int* __restrict__ ei) {
    int e = blockIdx.x * blockDim.x + threadIdx.x;
    if (e < EE) atomicAdd(&g_cnt[ei[EE + e]], 1);
}

// ---------------- exclusive scan (scan1 also emits dinv) ----------------
__global__ void scan1() {
    __shared__ int s[256];
    int tid = threadIdx.x;
    int i = blockIdx.x * 256 + tid;
    int v = (i < NN) ? g_cnt[i] : 0;
    if (i < NN) g_dinv[i] = rsqrtf(1.0f + (float)v);
    s[tid] = v;
    __syncthreads();
#pragma unroll
    for (int off = 1; off < 256; off <<= 1) {
        int t = (tid >= off) ? s[tid - off] : 0;
        __syncthreads();
        s[tid] += t;
        __syncthreads();
    }
    if (i < NN) g_rowptr[i] = s[tid] - v;
    if (tid == 255) g_bsum[blockIdx.x] = s[255];
}
__global__ void scan2() {
    __shared__ int s[512];
    int tid = threadIdx.x;
    int v = (tid < NB_SCAN) ? g_bsum[tid] : 0;
    s[tid] = v;
    __syncthreads();
#pragma unroll
    for (int off = 1; off < 512; off <<= 1) {
        int t = (tid >= off) ? s[tid - off] : 0;
        __syncthreads();
        s[tid] += t;
        __syncthreads();
    }
    if (tid < NB_SCAN) g_boff[tid] = s[tid] - v;
}
__global__ void scan3() {
    int i = blockIdx.x * blockDim.x + threadIdx.x;
    if (i < NN) {
        g_rowptr[i] += g_boff[i >> 8];
        g_fill[i] = 0;
    }
}
__global__ void csr_fill(const int* __restrict__ ei) {
    int e = blockIdx.x * blockDim.x + threadIdx.x;
    if (e < EE) {
        int s = ei[e];
        int d = ei[EE + e];
        int pos = g_rowptr[d] + atomicAdd(&g_fill[d], 1);
        g_col[pos] = s;
    }
}

// ---------------- x -> fp16 (covers padding) ----------------
__global__ void convert_x(const float* __restrict__ X) {
    int i = blockIdx.x * blockDim.x + threadIdx.x;  // over NPAD*64 float2
    if (i < NPAD * 64) {
        float2 v = (i < NN * 64) ? ((const float2*)X)[i] : make_float2(0.f, 0.f);
        ((__half2*)g_a16)[i] = __floats2half2_rn(v.x, v.y);
    }
}

// ---------------- tensor-core GEMM (fp16 single-term, cp.async A pipeline) -----
__device__ __forceinline__ void mma_f16(float c[4], unsigned a0, unsigned a1,
                                        unsigned a2, unsigned a3, unsigned b0,
                                        unsigned b1) {
    asm volatile(
        "mma.sync.aligned.m16n8k16.row.col.f32.f16.f16.f32 "
        "{%0,%1,%2,%3}, {%4,%5,%6,%7}, {%8,%9}, {%0,%1,%2,%3};"
        : "+f"(c[0]), "+f"(c[1]), "+f"(c[2]), "+f"(c[3])
        : "r"(a0), "r"(a1), "r"(a2), "r"(a3), "r"(b0), "r"(b1));
}
__device__ __forceinline__ void ldsm4t(unsigned& r0, unsigned& r1, unsigned& r2,
                                       unsigned& r3, unsigned saddr) {
    asm volatile(
        "ldmatrix.sync.aligned.m8n8.x4.trans.shared.b16 {%0,%1,%2,%3}, [%4];"
        : "=r"(r0), "=r"(r1), "=r"(r2), "=r"(r3)
        : "r"(saddr));
}
__device__ __forceinline__ void ldsm4(unsigned& r0, unsigned& r1, unsigned& r2,
                                      unsigned& r3, unsigned saddr) {
    asm volatile(
        "ldmatrix.sync.aligned.m8n8.x4.shared.b16 {%0,%1,%2,%3}, [%4];"
        : "=r"(r0), "=r"(r1), "=r"(r2), "=r"(r3)
        : "r"(saddr));
}

// stage one 128x16 fp16 A slab into smem buffer `buf` via cp.async (256 thr)
__device__ __forceinline__ void stageA(unsigned sa0, int buf, const __half* aP,
                                       int k0, int tid) {
    int row = tid >> 1;   // 0..127
    int half = tid & 1;   // k-halves 0-7 / 8-15
    const __half* src = aP + row * 128 + k0 + half * 8;
    unsigned dst = sa0 + ((unsigned)((buf * 128 + row) * ASTR + half * 8)) * 2;
    asm volatile("cp.async.cg.shared.global [%0], [%1], 16;\n" ::"r"(dst),
                 "l"(src));
}

__global__ __launch_bounds__(256, 2) void gemm_mma(const float* __restrict__ W) {
    extern __shared__ __half sw[];
    __half* Wh = sw;  // [128][KSTR]
    int tid = threadIdx.x;

    unsigned sbase = (unsigned)__cvta_generic_to_shared(sw);
    unsigned swh = sbase;
    unsigned sa0 = sbase + 128 * KSTR * 2;  // A region: [2 buf][128][ASTR]

    int row0 = blockIdx.x * 128;
    const __half* aP = g_a16 + (size_t)row0 * 128;

    stageA(sa0, 0, aP, 0, tid);
    asm volatile("cp.async.commit_group;\n");
    stageA(sa0, 1, aP, 16, tid);
    asm volatile("cp.async.commit_group;\n");

    for (int i = tid; i < 128 * 128; i += 256) {
        int k = i >> 7, n = i & 127;
        Wh[k * KSTR + n] = __float2half(W[i]);
    }
    __syncthreads();

    int warp = tid >> 5, lane = tid & 31;
    int g = lane >> 2, t = lane & 3;

    int q = lane >> 3, r = lane & 7;
    int kk_off = (r + ((q & 1) << 3)) * (KSTR * 2);
    int nn_off = ((q >> 1) << 3) * 2;

    unsigned aoff = ((unsigned)((warp * 16 + (lane & 15)) * ASTR + ((lane & 16) >> 1))) * 2;

    float c[16][4];
#pragma unroll
    for (int i = 0; i < 16; i++)
#pragma unroll
        for (int j = 0; j < 4; j++) c[i][j] = 0.f;

    for (int kb = 0; kb < 8; kb++) {
        if (kb < 7)
            asm volatile("cp.async.wait_group 1;\n");
        else
            asm volatile("cp.async.wait_group 0;\n");
        __syncthreads();

        int buf = kb & 1;
        unsigned ah0, ah1, ah2, ah3;
        ldsm4(ah0, ah1, ah2, ah3, sa0 + (unsigned)(buf * 128 * ASTR) * 2 + aoff);

        unsigned kbase = (unsigned)(kb * 16 * (KSTR * 2)) + kk_off + nn_off;
#pragma unroll
        for (int p = 0; p < 8; p++) {
            unsigned noff = kbase + p * 32;
            unsigned bh0, bh1, bh2, bh3;
            ldsm4t(bh0, bh1, bh2, bh3, swh + noff);
            mma_f16(c[2 * p],     ah0, ah1, ah2, ah3, bh0, bh1);
            mma_f16(c[2 * p + 1], ah0, ah1, ah2, ah3, bh2, bh3);
        }
        __syncthreads();
        if (kb < 6) {
            stageA(sa0, buf, aP, (kb + 2) * 16, tid);
            asm volatile("cp.async.commit_group;\n");
        }
    }

    int ra = row0 + warp * 16 + g, rb = ra + 8;
    float da = (ra < NN) ? g_dinv[ra] : 0.f;
    float db = (rb < NN) ? g_dinv[rb] : 0.f;
#pragma unroll
    for (int nt = 0; nt < 16; nt++) {
        int col = nt * 8 + t * 2;
        if (ra < NN)
            *(__half2*)&g_hh[(size_t)ra * 128 + col] =
                __floats2half2_rn(da * c[nt][0], da * c[nt][1]);
        if (rb < NN)
            *(__half2*)&g_hh[(size_t)rb * 128 + col] =
                __floats2half2_rn(db * c[nt][2], db * c[nt][3]);
    }
}

// ---------------- pool encode ----------------
__device__ __forceinline__ unsigned enc_f(float x) {
    unsigned u = __float_as_uint(x);
    return (u & 0x80000000u) ? ~u : (u | 0x80000000u);
}
__device__ __forceinline__ float dec_f(unsigned e) {
    return (e & 0x80000000u) ? __uint_as_float(e ^ 0x80000000u)
                             : __uint_as_float(~e);
}

// ---------------- fused gather (fp16 h, prescaled; 4-deep load batch) ----------
__global__ void gather_fused(const float* __restrict__ bias,
                             const int* __restrict__ batch, int do_pool) {
    int warp = (blockIdx.x * blockDim.x + threadIdx.x) >> 5;
    int lane = threadIdx.x & 31;
    if (warp >= NN) return;
    int d = warp;
    int beg = g_rowptr[d];
    int end = beg + g_cnt[d];
    const uint2* h2 = (const uint2*)g_hh;  // 4 halves per uint2; 32 per row

    float4 acc = make_float4(0.f, 0.f, 0.f, 0.f);
    for (int base = beg; base < end; base += 32) {
        int n = min(32, end - base);
        int c = (lane < n) ? g_col[base + lane] : 0;
        int j = 0;
        for (; j + 4 <= n; j += 4) {
            int s0 = __shfl_sync(0xffffffffu, c, j);
            int s1 = __shfl_sync(0xffffffffu, c, j + 1);
            int s2 = __shfl_sync(0xffffffffu, c, j + 2);
            int s3 = __shfl_sync(0xffffffffu, c, j + 3);
            uint2 v0 = h2[(size_t)s0 * 32 + lane];
            uint2 v1 = h2[(size_t)s1 * 32 + lane];
            uint2 v2 = h2[(size_t)s2 * 32 + lane];
            uint2 v3 = h2[(size_t)s3 * 32 + lane];
            float2 a0 = __half22float2(*(__half2*)&v0.x);
            float2 b0 = __half22float2(*(__half2*)&v0.y);
            float2 a1 = __half22float2(*(__half2*)&v1.x);
            float2 b1 = __half22float2(*(__half2*)&v1.y);
            float2 a2 = __half22float2(*(__half2*)&v2.x);
            float2 b2 = __half22float2(*(__half2*)&v2.y);
            float2 a3 = __half22float2(*(__half2*)&v3.x);
            float2 b3 = __half22float2(*(__half2*)&v3.y);
            acc.x += (a0.x + a1.x) + (a2.x + a3.x);
            acc.y += (a0.y + a1.y) + (a2.y + a3.y);
            acc.z += (b0.x + b1.x) + (b2.x + b3.x);
            acc.w += (b0.y + b1.y) + (b2.y + b3.y);
        }
        for (; j < n; j++) {
            int s = __shfl_sync(0xffffffffu, c, j);
            uint2 hv = h2[(size_t)s * 32 + lane];
            float2 f0 = __half22float2(*(__half2*)&hv.x);
            float2 f1 = __half22float2(*(__half2*)&hv.y);
            acc.x += f0.x;
            acc.y += f0.y;
            acc.z += f1.x;
            acc.w += f1.y;
        }
    }
    float dd = g_dinv[d];
    uint2 hsv = h2[(size_t)d * 32 + lane];  // = dinv_d * h_d (fp16)
    float2 s0 = __half22float2(*(__half2*)&hsv.x);
    float2 s1 = __half22float2(*(__half2*)&hsv.y);
    float4 bb = *(const float4*)&bias[lane * 4];
    float vx = dd * (acc.x + s0.x) + bb.x;
    float vy = dd * (acc.y + s0.y) + bb.y;
    float vz = dd * (acc.z + s1.x) + bb.z;
    float vw = dd * (acc.w + s1.y) + bb.w;
    vx = vx > 0.f ? vx : expm1f(vx);
    vy = vy > 0.f ? vy : expm1f(vy);
    vz = vz > 0.f ? vz : expm1f(vz);
    vw = vw > 0.f ? vw : expm1f(vw);

    if (!do_pool) {
        __half2* pa = (__half2*)g_a16 + (size_t)d * 64 + lane * 2;
        pa[0] = __floats2half2_rn(vx, vy);
        pa[1] = __floats2half2_rn(vz, vw);
    } else {
        int g = batch[d];
        unsigned* p = &g_pool[g * 128 + lane * 4];
        atomicMax(&p[0], enc_f(vx));
        atomicMax(&p[1], enc_f(vy));
        atomicMax(&p[2], enc_f(vz));
        atomicMax(&p[3], enc_f(vw));
    }
}

// ---------------- head ----------------
__global__ void head(const float* __restrict__ Wl, const float* __restrict__ bl,
                     float* __restrict__ out) {
    int warp = (blockIdx.x * blockDim.x + threadIdx.x) >> 5;
    int lane = threadIdx.x & 31;
    if (warp >= GG) return;
    float part[CC];
#pragma unroll
    for (int c = 0; c < CC; c++) part[c] = 0.f;
    for (int f = lane; f < HH; f += 32) {
        float p = dec_f(g_pool[warp * HH + f]);
        if (p < -3.0e38f) p = 0.0f;
#pragma unroll
        for (int c = 0; c < CC; c++) part[c] += p * Wl[f * CC + c];
    }
#pragma unroll
    for (int c = 0; c < CC; c++)
        for (int off = 16; off; off >>= 1)
            part[c] += __shfl_xor_sync(0xffffffffu, part[c], off);
    if (lane == 0) {
        float lg[CC];
        float m = -3.4e38f;
#pragma unroll
        for (int c = 0; c < CC; c++) {
            lg[c] = part[c] + bl[c];
            m = fmaxf(m, lg[c]);
        }
        float sum = 0.f;
#pragma unroll
        for (int c = 0; c < CC; c++) {
            lg[c] = expf(lg[c] - m);
            sum += lg[c];
        }
        float inv = 1.0f / sum;
#pragma unroll
        for (int c = 0; c < CC; c++) out[warp * CC + c] = lg[c] * inv;
    }
}

// ---------------- launcher ----------------
extern "C" void kernel_launch(void* const* d_in, const int* in_sizes, int n_in,
                              void* d_out, int out_size) {
    const float* x = (const float*)d_in[0];
    const int* ei = (const int*)d_in[1];
    const int* batch = (const int*)d_in[2];
    const float* W0 = (const float*)d_in[3];
    const float* b0 = (const float*)d_in[4];
    const float* W1 = (const float*)d_in[5];
    const float* b1 = (const float*)d_in[6];
    const float* W2 = (const float*)d_in[7];
    const float* b2 = (const float*)d_in[8];
    const float* Wl = (const float*)d_in[9];
    const float* bl = (const float*)d_in[10];
    float* out = (float*)d_out;

    const int T = 256;
    const int gemm_smem = 128 * KSTR * 2 + 2 * 128 * ASTR * 2;  // 47104 B
    cudaFuncSetAttribute(gemm_mma, cudaFuncAttributeMaxDynamicSharedMemorySize,
                         gemm_smem);

    const int gemm_blocks = NPAD / 128;  // 782
    const int gather_blocks = (NN * 32 + T - 1) / T;

    init_all<<<(GG * HH + T - 1) / T, T>>>();

    if (s_ok) {
        // fork: CSR build on side stream, convert+gemm0 on main stream
        cudaEventRecord(s_e0, 0);
        cudaStreamWaitEvent(s_side, s_e0, 0);
        deg_count<<<(EE + T - 1) / T, T, 0, s_side>>>(ei);
        scan1<<<NB_SCAN, 256, 0, s_side>>>();
        cudaEventRecord(s_edinv, s_side);        // g_dinv ready
        scan2<<<1, 512, 0, s_side>>>();
        scan3<<<(NN + T - 1) / T, T, 0, s_side>>>();
        csr_fill<<<(EE + T - 1) / T, T, 0, s_side>>>(ei);
        cudaEventRecord(s_ecsr, s_side);         // CSR ready

        convert_x<<<(NPAD * 64 + T - 1) / T, T>>>(x);
        cudaStreamWaitEvent(0, s_edinv, 0);      // gemm0 epilogue reads g_dinv
        gemm_mma<<<gemm_blocks, T, gemm_smem>>>(W0);
        cudaStreamWaitEvent(0, s_ecsr, 0);       // join before first gather
    } else {
        deg_count<<<(EE + T - 1) / T, T>>>(ei);
        scan1<<<NB_SCAN, 256>>>();
        scan2<<<1, 512>>>();
        scan3<<<(NN + T - 1) / T, T>>>();
        csr_fill<<<(EE + T - 1) / T, T>>>(ei);
        convert_x<<<(NPAD * 64 + T - 1) / T, T>>>(x);
        gemm_mma<<<gemm_blocks, T, gemm_smem>>>(W0);
    }

    gather_fused<<<gather_blocks, T>>>(b0, batch, 0);
    gemm_mma<<<gemm_blocks, T, gemm_smem>>>(W1);
    gather_fused<<<gather_blocks, T>>>(b1, batch, 0);
    gemm_mma<<<gemm_blocks, T, gemm_smem>>>(W2);
    gather_fused<<<gather_blocks, T>>>(b2, batch, 1);

    head<<<(GG + 7) / 8, T>>>(Wl, bl, out);
}